// round 9
// baseline (speedup 1.0000x reference)
#include <cuda_runtime.h>
#include <math.h>

#define NTOK 65536
#define ZQ_OFF   0
#define CODES_OFF 33554432
#define LAT_OFF   34144256
#define COMMIT_OFF 38862848

// ---------------- device scratch (no allocation) ----------------
__device__ float g_P[72 * NTOK];      // [q][tok], q = i*8+d
__device__ float g_Q[72 * NTOK];      // selected raw code vecs, [q][tok]
__device__ float g_WinT[512 * 72];    // [c][q]
__device__ float g_WoT[512 * 72];     // [c][q]
__device__ float g_M[81 * 64];        // M[i][j][d][e]
__device__ float g_cvec[81 * 8];      // W_in_i @ out_b_j
__device__ float g_Cbias[512];        // sum_j out_b_j
__device__ float g_cbn[9 * 8 * 128 * 8];  // normalized codebooks
__device__ float g_sb[9 * 8 * 128];       // -0.5*|cbn|^2
__device__ float g_cn[9 * 8 * 128];       // raw norms
__device__ float g_cnt[72];
__device__ float g_ps[72];
__device__ float g_commit[1];

// ---------------- packed f32x2 helpers ----------------
__device__ __forceinline__ unsigned long long pack2(float lo, float hi) {
    unsigned long long r;
    asm("mov.b64 %0, {%1,%2};" : "=l"(r) : "f"(lo), "f"(hi));
    return r;
}
__device__ __forceinline__ void unpack2(unsigned long long v, float& lo, float& hi) {
    asm("mov.b64 {%0,%1}, %2;" : "=f"(lo), "=f"(hi) : "l"(v));
}
__device__ __forceinline__ unsigned long long fma2(unsigned long long a,
                                                   unsigned long long b,
                                                   unsigned long long c) {
    unsigned long long r;
    asm("fma.rn.f32x2 %0, %1, %2, %3;" : "=l"(r) : "l"(a), "l"(b), "l"(c));
    return r;
}

// ================================================================
// prep1: weight-norm weights (transposed), codebook norms, Cbias, zeros
// ================================================================
__global__ void prep1_kernel(const float* __restrict__ in_v, const float* __restrict__ in_g,
                             const float* __restrict__ out_v, const float* __restrict__ out_g,
                             const float* __restrict__ out_b, const float* __restrict__ cb) {
    int tid = blockIdx.x * blockDim.x + threadIdx.x;
    if (tid < 72) {
        const float* v = in_v + (size_t)tid * 512;
        float s = 0.f;
        for (int c = 0; c < 512; c++) s = fmaf(v[c], v[c], s);
        float inv = in_g[tid] / sqrtf(s);
        for (int c = 0; c < 512; c++) g_WinT[c * 72 + tid] = v[c] * inv;
    } else if (tid < 72 + 4608) {
        int rid = tid - 72;                       // j*512 + c
        int j = rid >> 9, c = rid & 511;
        const float* v = out_v + (size_t)rid * 8;
        float s = 0.f;
#pragma unroll
        for (int d = 0; d < 8; d++) s = fmaf(v[d], v[d], s);
        float inv = out_g[rid] / sqrtf(s);
#pragma unroll
        for (int d = 0; d < 8; d++) g_WoT[c * 72 + j * 8 + d] = v[d] * inv;
    } else if (tid < 4680 + 512) {
        int c = tid - 4680;
        float s = 0.f;
        for (int j = 0; j < 9; j++) s += out_b[j * 512 + c];
        g_Cbias[c] = s;
    } else if (tid < 5192 + 9216) {
        int rid = tid - 5192;                     // i*1024 + e*128 + k
        const float* v = cb + (size_t)rid * 8;
        float s = 0.f;
#pragma unroll
        for (int d = 0; d < 8; d++) s = fmaf(v[d], v[d], s);
        float rawn = sqrtf(s);
        float m = fmaxf(rawn, 1e-12f);
        float s2 = 0.f;
#pragma unroll
        for (int d = 0; d < 8; d++) {
            float cn = v[d] / m;
            g_cbn[rid * 8 + d] = cn;
            s2 = fmaf(cn, cn, s2);
        }
        g_sb[rid] = -0.5f * s2;
        g_cn[rid] = rawn;
    } else if (tid < 14408 + 145) {
        int r = tid - 14408;
        if (r < 72) g_cnt[r] = 0.f;
        else if (r < 144) g_ps[r - 72] = 0.f;
        else g_commit[0] = 0.f;
    }
}

// ================================================================
// prep2: M[i][j] = W_in_i @ W_out_j, cvec[i][j] = W_in_i @ out_b_j
// ================================================================
__global__ void prep2_kernel(const float* __restrict__ out_b) {
    int ij = blockIdx.x;              // i*9+j
    int i = ij / 9, j = ij % 9;
    int tid = threadIdx.x;            // 72 threads
    if (tid < 64) {
        int d = tid >> 3, e = tid & 7;
        float s = 0.f;
        for (int c = 0; c < 512; c++)
            s = fmaf(g_WinT[c * 72 + i * 8 + d], g_WoT[c * 72 + j * 8 + e], s);
        g_M[ij * 64 + d * 8 + e] = s;
    } else {
        int d = tid - 64;
        float s = 0.f;
        for (int c = 0; c < 512; c++)
            s = fmaf(g_WinT[c * 72 + i * 8 + d], out_b[j * 512 + c], s);
        g_cvec[ij * 8 + d] = s;
    }
}

// ================================================================
// kernel A: P[q][tok] = W_in_all @ z + in_b   (packed f32x2 over q-pairs)
// ================================================================
__global__ __launch_bounds__(256) void kA_kernel(const float* __restrict__ z,
                                                 const float* __restrict__ in_b) {
    extern __shared__ float ws[];     // 512*72 floats
    int tid = threadIdx.x;
    int tok = blockIdx.x * 256 + tid;
    int b = tok >> 12, t = tok & 4095;

    const float4* wsrc = (const float4*)g_WinT;
    float4* wdst = (float4*)ws;
#pragma unroll
    for (int j = 0; j < 36; j++) wdst[tid + j * 256] = wsrc[tid + j * 256];
    __syncthreads();

    unsigned long long acc[36];
#pragma unroll
    for (int m = 0; m < 36; m++) acc[m] = 0ULL;

    const float* zp = z + (size_t)b * 512 * 4096 + t;
#pragma unroll 1
    for (int c0 = 0; c0 < 512; c0 += 16) {
        float zr[16];
#pragma unroll
        for (int cc = 0; cc < 16; cc++) zr[cc] = zp[(size_t)(c0 + cc) * 4096];
#pragma unroll
        for (int cc = 0; cc < 16; cc++) {
            unsigned long long z2 = pack2(zr[cc], zr[cc]);
            const ulonglong2* wrow = (const ulonglong2*)(ws + (c0 + cc) * 72);
#pragma unroll
            for (int m = 0; m < 18; m++) {
                ulonglong2 w = wrow[m];
                acc[2 * m]     = fma2(w.x, z2, acc[2 * m]);
                acc[2 * m + 1] = fma2(w.y, z2, acc[2 * m + 1]);
            }
        }
    }
#pragma unroll
    for (int m = 0; m < 36; m++) {
        float lo, hi;
        unpack2(acc[m], lo, hi);
        g_P[(2 * m) * NTOK + tok]     = lo + __ldg(&in_b[2 * m]);
        g_P[(2 * m + 1) * NTOK + tok] = hi + __ldg(&in_b[2 * m + 1]);
    }
}

// ================================================================
// kernel B: per-token sequential RVQ state machine (9 stages)
// ================================================================
__global__ __launch_bounds__(256) void kB_kernel(const float* __restrict__ r_w1,
                                                 const float* __restrict__ r_b1,
                                                 const float* __restrict__ r_w2,
                                                 const float* __restrict__ r_b2,
                                                 float* __restrict__ out) {
    __shared__ float4 s_cb[8 * 257];      // expert stride 1028 floats: conflict-free
    __shared__ float s_sb[8 * 132];
    __shared__ float s_cn[8 * 132];
    __shared__ float s_cnt[72], s_ps[72];
    __shared__ float s_red[8];

    int tid = threadIdx.x, lane = tid & 31, wid = tid >> 5;
    int tok = blockIdx.x * 256 + tid;
    int b = tok >> 12, t = tok & 4095;

    if (tid < 72) { s_cnt[tid] = 0.f; s_ps[tid] = 0.f; }

    float commit_loc = 0.f;
    float* out_codes = out + CODES_OFF;
    float* out_lat = out + LAT_OFF;

#pragma unroll 1
    for (int i = 0; i < 9; i++) {
        __syncthreads();
        {   // stage codebook tables into padded smem
            const float4* src = (const float4*)(g_cbn + (size_t)i * 8192);
#pragma unroll
            for (int j = 0; j < 8; j++) {
                int g = tid + j * 256;        // 2048 float4
                int e = g >> 8, r = g & 255;
                s_cb[e * 257 + r] = src[g];
            }
#pragma unroll
            for (int j = 0; j < 4; j++) {
                int g = tid + j * 256;        // 1024
                int e = g >> 7, k = g & 127;
                s_sb[e * 132 + k] = g_sb[i * 1024 + g];
                s_cn[e * 132 + k] = g_cn[i * 1024 + g];
            }
        }
        __syncthreads();

        // z_e = P_i - sum_{j<i} (M_ij q_j + c_ij)
        float ze[8];
#pragma unroll
        for (int d = 0; d < 8; d++) ze[d] = g_P[(i * 8 + d) * NTOK + tok];
        for (int j = 0; j < i; j++) {
            float qj[8];
#pragma unroll
            for (int e = 0; e < 8; e++) qj[e] = g_Q[(j * 8 + e) * NTOK + tok];
            const float* Mij = g_M + (i * 9 + j) * 64;
            const float* cij = g_cvec + (i * 9 + j) * 8;
#pragma unroll
            for (int d = 0; d < 8; d++) {
                float s = __ldg(&cij[d]);
#pragma unroll
                for (int e = 0; e < 8; e++) s = fmaf(__ldg(&Mij[d * 8 + e]), qj[e], s);
                ze[d] -= s;
            }
        }

        // latents output
        {
            float4* lp = (float4*)(out_lat + ((size_t)((b * 9 + i) * 4096 + t)) * 8);
            lp[0] = make_float4(ze[0], ze[1], ze[2], ze[3]);
            lp[1] = make_float4(ze[4], ze[5], ze[6], ze[7]);
        }

        // router
        float h[8];
#pragma unroll
        for (int hh = 0; hh < 8; hh++) {
            float s = __ldg(&r_b1[i * 8 + hh]);
#pragma unroll
            for (int d = 0; d < 8; d++) s = fmaf(__ldg(&r_w1[(i * 8 + hh) * 8 + d]), ze[d], s);
            h[hh] = fmaxf(s, 0.f);
        }
        float lg[8];
        float lmax = -3.4e38f;
        int estar = 0;
#pragma unroll
        for (int e = 0; e < 8; e++) {
            float s = __ldg(&r_b2[i * 8 + e]);
#pragma unroll
            for (int hh = 0; hh < 8; hh++) s = fmaf(__ldg(&r_w2[(i * 8 + e) * 8 + hh]), h[hh], s);
            lg[e] = s;
            if (s > lmax) { lmax = s; estar = e; }
        }

        // softmax (for aux loss only)
        float pr[8], psum = 0.f;
#pragma unroll
        for (int e = 0; e < 8; e++) { pr[e] = expf(lg[e] - lmax); psum += pr[e]; }
        float pinv = 1.f / psum;

        // aux accumulation: warp reduce then lane0 smem atomics
#pragma unroll
        for (int e = 0; e < 8; e++) {
            float v = pr[e] * pinv;
            v += __shfl_xor_sync(0xffffffffu, v, 16);
            v += __shfl_xor_sync(0xffffffffu, v, 8);
            v += __shfl_xor_sync(0xffffffffu, v, 4);
            v += __shfl_xor_sync(0xffffffffu, v, 2);
            v += __shfl_xor_sync(0xffffffffu, v, 1);
            unsigned bal = __ballot_sync(0xffffffffu, estar == e);
            if (lane == 0) {
                atomicAdd(&s_ps[i * 8 + e], v);
                atomicAdd(&s_cnt[i * 8 + e], (float)__popc(bal));
            }
        }

        // normalized encoding
        float nn = 0.f;
#pragma unroll
        for (int d = 0; d < 8; d++) nn = fmaf(ze[d], ze[d], nn);
        float inv = 1.0f / fmaxf(sqrtf(nn), 1e-12f);
        float enc[8];
#pragma unroll
        for (int d = 0; d < 8; d++) enc[d] = ze[d] * inv;

        // nearest neighbor in selected expert (first max wins)
        const float4* cpe = s_cb + estar * 257;
        const float* sbe = s_sb + estar * 132;
        float best = -3.4e38f;
        int bk = 0;
#pragma unroll 4
        for (int k = 0; k < 128; k++) {
            float4 a = cpe[2 * k], c = cpe[2 * k + 1];
            float dt = fmaf(enc[0], a.x, fmaf(enc[1], a.y, fmaf(enc[2], a.z, enc[3] * a.w)));
            dt = fmaf(enc[4], c.x, fmaf(enc[5], c.y, fmaf(enc[6], c.z, fmaf(enc[7], c.w, dt))));
            dt += sbe[k];
            if (dt > best) { best = dt; bk = k; }
        }

        // selected raw code vector q = cbn * rawnorm
        float cn = s_cn[estar * 132 + bk];
        float4 a = cpe[2 * bk], c = cpe[2 * bk + 1];
        float q[8] = { a.x * cn, a.y * cn, a.z * cn, a.w * cn,
                       c.x * cn, c.y * cn, c.z * cn, c.w * cn };
#pragma unroll
        for (int d = 0; d < 8; d++) {
            g_Q[(i * 8 + d) * NTOK + tok] = q[d];
            float df = ze[d] - q[d];
            commit_loc = fmaf(df, df, commit_loc);
        }
        out_codes[(size_t)(b * 9 + i) * 4096 + t] = (float)(bk + 128 * estar);
    }

    // reduce commitment
    commit_loc += __shfl_xor_sync(0xffffffffu, commit_loc, 16);
    commit_loc += __shfl_xor_sync(0xffffffffu, commit_loc, 8);
    commit_loc += __shfl_xor_sync(0xffffffffu, commit_loc, 4);
    commit_loc += __shfl_xor_sync(0xffffffffu, commit_loc, 2);
    commit_loc += __shfl_xor_sync(0xffffffffu, commit_loc, 1);
    __syncthreads();                       // all smem atomics done
    if (lane == 0) s_red[wid] = commit_loc;
    __syncthreads();
    if (tid == 0) {
        float s = 0.f;
        for (int w = 0; w < 8; w++) s += s_red[w];
        atomicAdd(&g_commit[0], s);
    }
    if (tid < 72) {
        atomicAdd(&g_cnt[tid], s_cnt[tid]);
        atomicAdd(&g_ps[tid], s_ps[tid]);
    }
}

// ================================================================
// kernel C: z_q[b][c][t] = W_out_cat @ Q + Cbias  (packed f32x2)
// ================================================================
__global__ __launch_bounds__(256) void kC_kernel(float* __restrict__ out) {
    extern __shared__ float sm[];          // 512*72 + 512 floats
    float* ws = sm;
    float* cbias = sm + 36864;
    int tid = threadIdx.x;
    int tok = blockIdx.x * 256 + tid;
    int b = tok >> 12, t = tok & 4095;

    const float4* wsrc = (const float4*)g_WoT;
    float4* wdst = (float4*)ws;
#pragma unroll
    for (int j = 0; j < 36; j++) wdst[tid + j * 256] = wsrc[tid + j * 256];
    for (int j = tid; j < 512; j += 256) cbias[j] = g_Cbias[j];
    __syncthreads();

    unsigned long long q2[36];
#pragma unroll
    for (int m = 0; m < 36; m++)
        q2[m] = pack2(g_Q[(2 * m) * NTOK + tok], g_Q[(2 * m + 1) * NTOK + tok]);

    float* op = out + (size_t)b * 512 * 4096 + t;
#pragma unroll 2
    for (int c = 0; c < 512; c++) {
        const ulonglong2* wr = (const ulonglong2*)(ws + c * 72);
        unsigned long long ac0 = 0ULL, ac1 = 0ULL, ac2 = 0ULL, ac3 = 0ULL;
#pragma unroll
        for (int m = 0; m < 9; m++) {
            ulonglong2 w0 = wr[2 * m];
            ulonglong2 w1 = wr[2 * m + 1];
            ac0 = fma2(w0.x, q2[4 * m], ac0);
            ac1 = fma2(w0.y, q2[4 * m + 1], ac1);
            ac2 = fma2(w1.x, q2[4 * m + 2], ac2);
            ac3 = fma2(w1.y, q2[4 * m + 3], ac3);
        }
        float l0, h0, l1, h1, l2, h2, l3, h3;
        unpack2(ac0, l0, h0); unpack2(ac1, l1, h1);
        unpack2(ac2, l2, h2); unpack2(ac3, l3, h3);
        op[(size_t)c * 4096] = ((l0 + h0) + (l1 + h1)) + ((l2 + h2) + (l3 + h3)) + cbias[c];
    }
}

// ================================================================
// final: losses
// ================================================================
__global__ void kF_kernel(float* __restrict__ out) {
    __shared__ float sa[72];
    int tid = threadIdx.x;
    if (tid < 72) sa[tid] = g_cnt[tid] * g_ps[tid];
    __syncthreads();
    if (tid == 0) {
        float aux = 0.f;
        for (int q = 0; q < 72; q++) aux += sa[q];
        aux *= (1.f / 65536.f) * (1.f / 65536.f);
        float cm = g_commit[0] / 524288.f;    // /(16*4096*8)
        out[COMMIT_OFF] = cm;
        out[COMMIT_OFF + 1] = cm;             // codebook_loss == commitment_loss numerically
        out[COMMIT_OFF + 2] = aux;
    }
}

// ================================================================
extern "C" void kernel_launch(void* const* d_in, const int* in_sizes, int n_in,
                              void* d_out, int out_size) {
    const float* z     = (const float*)d_in[0];
    const float* in_v  = (const float*)d_in[1];
    const float* in_g  = (const float*)d_in[2];
    const float* in_b  = (const float*)d_in[3];
    const float* out_v = (const float*)d_in[4];
    const float* out_g = (const float*)d_in[5];
    const float* out_b = (const float*)d_in[6];
    const float* r_w1  = (const float*)d_in[7];
    const float* r_b1  = (const float*)d_in[8];
    const float* r_w2  = (const float*)d_in[9];
    const float* r_b2  = (const float*)d_in[10];
    const float* cb    = (const float*)d_in[11];
    float* out = (float*)d_out;

    cudaFuncSetAttribute(kA_kernel, cudaFuncAttributeMaxDynamicSharedMemorySize, 147456);
    cudaFuncSetAttribute(kC_kernel, cudaFuncAttributeMaxDynamicSharedMemorySize, 149504);

    prep1_kernel<<<57, 256>>>(in_v, in_g, out_v, out_g, out_b, cb);
    prep2_kernel<<<81, 72>>>(out_b);
    kA_kernel<<<256, 256, 147456>>>(z, in_b);
    kB_kernel<<<256, 256>>>(r_w1, r_b1, r_w2, r_b2, out);
    kC_kernel<<<256, 256, 149504>>>(out);
    kF_kernel<<<1, 128>>>(out);
}

// round 10
// speedup vs baseline: 1.0560x; 1.0560x over previous
#include <cuda_runtime.h>
#include <math.h>

#define NTOK 65536
#define ZQ_OFF   0
#define CODES_OFF 33554432
#define LAT_OFF   34144256
#define COMMIT_OFF 38862848

// ---------------- device scratch (no allocation) ----------------
__device__ float g_P[72 * NTOK];      // [q][tok], q = i*8+d
__device__ float g_Q[72 * NTOK];      // selected raw code vecs, [q][tok]
__device__ float g_WinT[512 * 72];    // [c][q]
__device__ float g_WoT[512 * 72];     // [c][q]
__device__ float g_M[81 * 64];        // M[i][j][d][e]
__device__ float g_cvec[81 * 8];      // W_in_i @ out_b_j
__device__ float g_Cbias[512];        // sum_j out_b_j
__device__ float g_cbn[9 * 8 * 128 * 8];  // normalized codebooks
__device__ float g_sb[9 * 8 * 128];       // -0.5*|cbn|^2
__device__ float g_cn[9 * 8 * 128];       // raw norms
__device__ float g_cnt[72];
__device__ float g_ps[72];
__device__ float g_commit[1];

// ---------------- packed f32x2 helpers ----------------
__device__ __forceinline__ unsigned long long pack2(float lo, float hi) {
    unsigned long long r;
    asm("mov.b64 %0, {%1,%2};" : "=l"(r) : "f"(lo), "f"(hi));
    return r;
}
__device__ __forceinline__ void unpack2(unsigned long long v, float& lo, float& hi) {
    asm("mov.b64 {%0,%1}, %2;" : "=f"(lo), "=f"(hi) : "l"(v));
}
__device__ __forceinline__ unsigned long long fma2(unsigned long long a,
                                                   unsigned long long b,
                                                   unsigned long long c) {
    unsigned long long r;
    asm("fma.rn.f32x2 %0, %1, %2, %3;" : "=l"(r) : "l"(a), "l"(b), "l"(c));
    return r;
}

// ================================================================
// prep1: weight-norm weights (transposed), codebook norms, Cbias, zeros
// ================================================================
__global__ void prep1_kernel(const float* __restrict__ in_v, const float* __restrict__ in_g,
                             const float* __restrict__ out_v, const float* __restrict__ out_g,
                             const float* __restrict__ out_b, const float* __restrict__ cb) {
    int tid = blockIdx.x * blockDim.x + threadIdx.x;
    if (tid < 72) {
        const float* v = in_v + (size_t)tid * 512;
        float s = 0.f;
        for (int c = 0; c < 512; c++) s = fmaf(v[c], v[c], s);
        float inv = in_g[tid] / sqrtf(s);
        for (int c = 0; c < 512; c++) g_WinT[c * 72 + tid] = v[c] * inv;
    } else if (tid < 72 + 4608) {
        int rid = tid - 72;                       // j*512 + c
        int j = rid >> 9, c = rid & 511;
        const float* v = out_v + (size_t)rid * 8;
        float s = 0.f;
#pragma unroll
        for (int d = 0; d < 8; d++) s = fmaf(v[d], v[d], s);
        float inv = out_g[rid] / sqrtf(s);
#pragma unroll
        for (int d = 0; d < 8; d++) g_WoT[c * 72 + j * 8 + d] = v[d] * inv;
    } else if (tid < 4680 + 512) {
        int c = tid - 4680;
        float s = 0.f;
        for (int j = 0; j < 9; j++) s += out_b[j * 512 + c];
        g_Cbias[c] = s;
    } else if (tid < 5192 + 9216) {
        int rid = tid - 5192;                     // i*1024 + e*128 + k
        const float* v = cb + (size_t)rid * 8;
        float s = 0.f;
#pragma unroll
        for (int d = 0; d < 8; d++) s = fmaf(v[d], v[d], s);
        float rawn = sqrtf(s);
        float m = fmaxf(rawn, 1e-12f);
        float s2 = 0.f;
#pragma unroll
        for (int d = 0; d < 8; d++) {
            float cn = v[d] / m;
            g_cbn[rid * 8 + d] = cn;
            s2 = fmaf(cn, cn, s2);
        }
        g_sb[rid] = -0.5f * s2;
        g_cn[rid] = rawn;
    } else if (tid < 14408 + 145) {
        int r = tid - 14408;
        if (r < 72) g_cnt[r] = 0.f;
        else if (r < 144) g_ps[r - 72] = 0.f;
        else g_commit[0] = 0.f;
    }
}

// ================================================================
// prep2: M[i][j] = W_in_i @ W_out_j, cvec[i][j] = W_in_i @ out_b_j
// ================================================================
__global__ void prep2_kernel(const float* __restrict__ out_b) {
    int ij = blockIdx.x;              // i*9+j
    int i = ij / 9, j = ij % 9;
    int tid = threadIdx.x;            // 72 threads
    if (tid < 64) {
        int d = tid >> 3, e = tid & 7;
        float s = 0.f;
        for (int c = 0; c < 512; c++)
            s = fmaf(g_WinT[c * 72 + i * 8 + d], g_WoT[c * 72 + j * 8 + e], s);
        g_M[ij * 64 + d * 8 + e] = s;
    } else {
        int d = tid - 64;
        float s = 0.f;
        for (int c = 0; c < 512; c++)
            s = fmaf(g_WinT[c * 72 + i * 8 + d], out_b[j * 512 + c], s);
        g_cvec[ij * 8 + d] = s;
    }
}

// ================================================================
// kernel A: P = W_in_all @ z + in_b.  2 tokens/thread register tile.
// grid 128 x 256 threads, 512 tokens per block, full weights in smem.
// ================================================================
__global__ __launch_bounds__(256) void kA_kernel(const float* __restrict__ z,
                                                 const float* __restrict__ in_b) {
    extern __shared__ float ws[];     // 512*72 floats
    int tid = threadIdx.x;
    int tok0 = blockIdx.x * 512 + 2 * tid;
    int b = tok0 >> 12, t0 = tok0 & 4095;

    const float4* wsrc = (const float4*)g_WinT;
    float4* wdst = (float4*)ws;
#pragma unroll
    for (int j = 0; j < 36; j++) wdst[tid + j * 256] = wsrc[tid + j * 256];
    __syncthreads();

    unsigned long long a0[36], a1[36];
#pragma unroll
    for (int m = 0; m < 36; m++) { a0[m] = 0ULL; a1[m] = 0ULL; }

    const float* zp = z + (size_t)b * 512 * 4096 + t0;
#pragma unroll 1
    for (int c0 = 0; c0 < 512; c0 += 8) {
        float2 zv[8];
#pragma unroll
        for (int cc = 0; cc < 8; cc++)
            zv[cc] = *(const float2*)(zp + (size_t)(c0 + cc) * 4096);
#pragma unroll
        for (int cc = 0; cc < 8; cc++) {
            unsigned long long za = pack2(zv[cc].x, zv[cc].x);
            unsigned long long zb = pack2(zv[cc].y, zv[cc].y);
            const ulonglong2* wrow = (const ulonglong2*)(ws + (c0 + cc) * 72);
#pragma unroll
            for (int m = 0; m < 18; m++) {
                ulonglong2 w = wrow[m];
                a0[2 * m]     = fma2(w.x, za, a0[2 * m]);
                a0[2 * m + 1] = fma2(w.y, za, a0[2 * m + 1]);
                a1[2 * m]     = fma2(w.x, zb, a1[2 * m]);
                a1[2 * m + 1] = fma2(w.y, zb, a1[2 * m + 1]);
            }
        }
    }
#pragma unroll
    for (int m = 0; m < 36; m++) {
        float l0, h0, l1, h1;
        unpack2(a0[m], l0, h0);
        unpack2(a1[m], l1, h1);
        float be = __ldg(&in_b[2 * m]), bo = __ldg(&in_b[2 * m + 1]);
        *(float2*)&g_P[(size_t)(2 * m) * NTOK + tok0]     = make_float2(l0 + be, l1 + be);
        *(float2*)&g_P[(size_t)(2 * m + 1) * NTOK + tok0] = make_float2(h0 + bo, h1 + bo);
    }
}

// ================================================================
// kernel B: per-token sequential RVQ, 2 threads per token
// (parity-split nearest-neighbor search). grid 512 x 256.
// ================================================================
__global__ __launch_bounds__(256) void kB_kernel(const float* __restrict__ r_w1,
                                                 const float* __restrict__ r_b1,
                                                 const float* __restrict__ r_w2,
                                                 const float* __restrict__ r_b2,
                                                 float* __restrict__ out) {
    __shared__ float4 s_cb[8 * 257];      // expert stride 1028 floats
    __shared__ float s_sb[8 * 132];
    __shared__ float s_cn[8 * 132];
    __shared__ float s_cnt[72], s_ps[72];
    __shared__ float s_red[8];

    int tid = threadIdx.x, lane = tid & 31, wid = tid >> 5;
    int half = tid & 1;
    int tok = blockIdx.x * 128 + (tid >> 1);
    int b = tok >> 12, t = tok & 4095;

    if (tid < 72) { s_cnt[tid] = 0.f; s_ps[tid] = 0.f; }

    float commit_loc = 0.f;
    float* out_codes = out + CODES_OFF;
    float* out_lat = out + LAT_OFF;

#pragma unroll 1
    for (int i = 0; i < 9; i++) {
        __syncthreads();
        {   // stage codebook tables into padded smem
            const float4* src = (const float4*)(g_cbn + (size_t)i * 8192);
#pragma unroll
            for (int j = 0; j < 8; j++) {
                int g = tid + j * 256;        // 2048 float4
                int e = g >> 8, r = g & 255;
                s_cb[e * 257 + r] = src[g];
            }
#pragma unroll
            for (int j = 0; j < 4; j++) {
                int g = tid + j * 256;        // 1024
                int e = g >> 7, k = g & 127;
                s_sb[e * 132 + k] = g_sb[i * 1024 + g];
                s_cn[e * 132 + k] = g_cn[i * 1024 + g];
            }
        }
        __syncthreads();

        // z_e = P_i - sum_{j<i} (M_ij q_j + c_ij)
        float ze[8];
#pragma unroll
        for (int d = 0; d < 8; d++) ze[d] = g_P[(size_t)(i * 8 + d) * NTOK + tok];
        for (int j = 0; j < i; j++) {
            float qj[8];
#pragma unroll
            for (int e = 0; e < 8; e++) qj[e] = g_Q[(size_t)(j * 8 + e) * NTOK + tok];
            const float* Mij = g_M + (i * 9 + j) * 64;
            const float* cij = g_cvec + (i * 9 + j) * 8;
#pragma unroll
            for (int d = 0; d < 8; d++) {
                float s = __ldg(&cij[d]);
#pragma unroll
                for (int e = 0; e < 8; e++) s = fmaf(__ldg(&Mij[d * 8 + e]), qj[e], s);
                ze[d] -= s;
            }
        }

        // latents output: each half writes its own float4
        {
            float4* lp = (float4*)(out_lat + ((size_t)((b * 9 + i) * 4096 + t)) * 8);
            lp[half] = half ? make_float4(ze[4], ze[5], ze[6], ze[7])
                            : make_float4(ze[0], ze[1], ze[2], ze[3]);
        }

        // router
        float h[8];
#pragma unroll
        for (int hh = 0; hh < 8; hh++) {
            float s = __ldg(&r_b1[i * 8 + hh]);
#pragma unroll
            for (int d = 0; d < 8; d++) s = fmaf(__ldg(&r_w1[(i * 8 + hh) * 8 + d]), ze[d], s);
            h[hh] = fmaxf(s, 0.f);
        }
        float lg[8];
        float lmax = -3.4e38f;
        int estar = 0;
#pragma unroll
        for (int e = 0; e < 8; e++) {
            float s = __ldg(&r_b2[i * 8 + e]);
#pragma unroll
            for (int hh = 0; hh < 8; hh++) s = fmaf(__ldg(&r_w2[(i * 8 + e) * 8 + hh]), h[hh], s);
            lg[e] = s;
            if (s > lmax) { lmax = s; estar = e; }
        }

        // softmax (for aux loss only)
        float pr[8], psum = 0.f;
#pragma unroll
        for (int e = 0; e < 8; e++) { pr[e] = expf(lg[e] - lmax); psum += pr[e]; }
        float pinv = 1.f / psum;

        // aux accumulation (half 0 only contributes)
#pragma unroll
        for (int e = 0; e < 8; e++) {
            float v = (half == 0) ? pr[e] * pinv : 0.f;
            v += __shfl_xor_sync(0xffffffffu, v, 16);
            v += __shfl_xor_sync(0xffffffffu, v, 8);
            v += __shfl_xor_sync(0xffffffffu, v, 4);
            v += __shfl_xor_sync(0xffffffffu, v, 2);
            v += __shfl_xor_sync(0xffffffffu, v, 1);
            unsigned bal = __ballot_sync(0xffffffffu, (half == 0) && (estar == e));
            if (lane == 0) {
                atomicAdd(&s_ps[i * 8 + e], v);
                atomicAdd(&s_cnt[i * 8 + e], (float)__popc(bal));
            }
        }

        // normalized encoding
        float nn = 0.f;
#pragma unroll
        for (int d = 0; d < 8; d++) nn = fmaf(ze[d], ze[d], nn);
        float inv = 1.0f / fmaxf(sqrtf(nn), 1e-12f);
        float enc[8];
#pragma unroll
        for (int d = 0; d < 8; d++) enc[d] = ze[d] * inv;

        // parity-split nearest neighbor: half 0 even k, half 1 odd k
        const float4* cpe = s_cb + estar * 257;
        const float* sbe = s_sb + estar * 132;
        float best = -3.4e38f;
        int bk = half;                 // first k of own parity
#pragma unroll 4
        for (int kk = 0; kk < 64; kk++) {
            int k = 2 * kk + half;
            float4 a = cpe[2 * k], c = cpe[2 * k + 1];
            float dt = fmaf(enc[0], a.x, fmaf(enc[1], a.y, fmaf(enc[2], a.z, enc[3] * a.w)));
            dt = fmaf(enc[4], c.x, fmaf(enc[5], c.y, fmaf(enc[6], c.z, fmaf(enc[7], c.w, dt))));
            dt += sbe[k];
            if (dt > best) { best = dt; bk = k; }
        }
        // combine with partner (same token, other parity); first-max = lowest k on tie
        float ob = __shfl_xor_sync(0xffffffffu, best, 1);
        int obk = __shfl_xor_sync(0xffffffffu, bk, 1);
        if (ob > best || (ob == best && obk < bk)) { best = ob; bk = obk; }

        // selected raw code vector q = cbn * rawnorm
        float cn = s_cn[estar * 132 + bk];
        float4 a = cpe[2 * bk], c = cpe[2 * bk + 1];
        float q[8] = { a.x * cn, a.y * cn, a.z * cn, a.w * cn,
                       c.x * cn, c.y * cn, c.z * cn, c.w * cn };
        if (half == 0) {
#pragma unroll
            for (int d = 0; d < 8; d++) {
                g_Q[(size_t)(i * 8 + d) * NTOK + tok] = q[d];
                float df = ze[d] - q[d];
                commit_loc = fmaf(df, df, commit_loc);
            }
            out_codes[(size_t)(b * 9 + i) * 4096 + t] = (float)(bk + 128 * estar);
        }
        // g_Q visibility for next stage: __syncthreads() at loop top orders it
    }

    // reduce commitment (only half-0 threads carry nonzero)
    commit_loc += __shfl_xor_sync(0xffffffffu, commit_loc, 16);
    commit_loc += __shfl_xor_sync(0xffffffffu, commit_loc, 8);
    commit_loc += __shfl_xor_sync(0xffffffffu, commit_loc, 4);
    commit_loc += __shfl_xor_sync(0xffffffffu, commit_loc, 2);
    commit_loc += __shfl_xor_sync(0xffffffffu, commit_loc, 1);
    __syncthreads();                       // all smem atomics done
    if (lane == 0) s_red[wid] = commit_loc;
    __syncthreads();
    if (tid == 0) {
        float s = 0.f;
        for (int w = 0; w < 8; w++) s += s_red[w];
        atomicAdd(&g_commit[0], s);
    }
    if (tid < 72) {
        atomicAdd(&g_cnt[tid], s_cnt[tid]);
        atomicAdd(&g_ps[tid], s_ps[tid]);
    }
}

// ================================================================
// kernel C: z_q = W_out_cat @ Q + Cbias.  2 tokens/thread register tile.
// grid 128 x 256 threads, 512 tokens per block.
// ================================================================
__global__ __launch_bounds__(256) void kC_kernel(float* __restrict__ out) {
    extern __shared__ float sm[];          // 512*72 + 512 floats
    float* ws = sm;
    float* cbias = sm + 36864;
    int tid = threadIdx.x;
    int tok0 = blockIdx.x * 512 + 2 * tid;
    int b = tok0 >> 12, t0 = tok0 & 4095;

    const float4* wsrc = (const float4*)g_WoT;
    float4* wdst = (float4*)ws;
#pragma unroll
    for (int j = 0; j < 36; j++) wdst[tid + j * 256] = wsrc[tid + j * 256];
    for (int j = tid; j < 512; j += 256) cbias[j] = g_Cbias[j];
    __syncthreads();

    unsigned long long q20[36], q21[36];
#pragma unroll
    for (int m = 0; m < 36; m++) {
        float2 va = *(const float2*)&g_Q[(size_t)(2 * m) * NTOK + tok0];
        float2 vb = *(const float2*)&g_Q[(size_t)(2 * m + 1) * NTOK + tok0];
        q20[m] = pack2(va.x, vb.x);    // token 0, q-pair (2m, 2m+1)
        q21[m] = pack2(va.y, vb.y);    // token 1
    }

    float* op = out + (size_t)b * 512 * 4096 + t0;
#pragma unroll 2
    for (int c = 0; c < 512; c++) {
        const ulonglong2* wr = (const ulonglong2*)(ws + c * 72);
        unsigned long long a00 = 0ULL, a01 = 0ULL, a02 = 0ULL, a03 = 0ULL;
        unsigned long long a10 = 0ULL, a11 = 0ULL, a12 = 0ULL, a13 = 0ULL;
#pragma unroll
        for (int m = 0; m < 9; m++) {
            ulonglong2 w0 = wr[2 * m];
            ulonglong2 w1 = wr[2 * m + 1];
            a00 = fma2(w0.x, q20[4 * m], a00);
            a01 = fma2(w0.y, q20[4 * m + 1], a01);
            a02 = fma2(w1.x, q20[4 * m + 2], a02);
            a03 = fma2(w1.y, q20[4 * m + 3], a03);
            a10 = fma2(w0.x, q21[4 * m], a10);
            a11 = fma2(w0.y, q21[4 * m + 1], a11);
            a12 = fma2(w1.x, q21[4 * m + 2], a12);
            a13 = fma2(w1.y, q21[4 * m + 3], a13);
        }
        float l0, h0, l1, h1, l2, h2, l3, h3;
        unpack2(a00, l0, h0); unpack2(a01, l1, h1);
        unpack2(a02, l2, h2); unpack2(a03, l3, h3);
        float r0 = ((l0 + h0) + (l1 + h1)) + ((l2 + h2) + (l3 + h3)) + cbias[c];
        unpack2(a10, l0, h0); unpack2(a11, l1, h1);
        unpack2(a12, l2, h2); unpack2(a13, l3, h3);
        float r1 = ((l0 + h0) + (l1 + h1)) + ((l2 + h2) + (l3 + h3)) + cbias[c];
        *(float2*)(op + (size_t)c * 4096) = make_float2(r0, r1);
    }
}

// ================================================================
// final: losses
// ================================================================
__global__ void kF_kernel(float* __restrict__ out) {
    __shared__ float sa[72];
    int tid = threadIdx.x;
    if (tid < 72) sa[tid] = g_cnt[tid] * g_ps[tid];
    __syncthreads();
    if (tid == 0) {
        float aux = 0.f;
        for (int q = 0; q < 72; q++) aux += sa[q];
        aux *= (1.f / 65536.f) * (1.f / 65536.f);
        float cm = g_commit[0] / 524288.f;    // /(16*4096*8)
        out[COMMIT_OFF] = cm;
        out[COMMIT_OFF + 1] = cm;             // codebook_loss == commitment_loss numerically
        out[COMMIT_OFF + 2] = aux;
    }
}

// ================================================================
extern "C" void kernel_launch(void* const* d_in, const int* in_sizes, int n_in,
                              void* d_out, int out_size) {
    const float* z     = (const float*)d_in[0];
    const float* in_v  = (const float*)d_in[1];
    const float* in_g  = (const float*)d_in[2];
    const float* in_b  = (const float*)d_in[3];
    const float* out_v = (const float*)d_in[4];
    const float* out_g = (const float*)d_in[5];
    const float* out_b = (const float*)d_in[6];
    const float* r_w1  = (const float*)d_in[7];
    const float* r_b1  = (const float*)d_in[8];
    const float* r_w2  = (const float*)d_in[9];
    const float* r_b2  = (const float*)d_in[10];
    const float* cb    = (const float*)d_in[11];
    float* out = (float*)d_out;

    cudaFuncSetAttribute(kA_kernel, cudaFuncAttributeMaxDynamicSharedMemorySize, 147456);
    cudaFuncSetAttribute(kC_kernel, cudaFuncAttributeMaxDynamicSharedMemorySize, 149504);

    prep1_kernel<<<57, 256>>>(in_v, in_g, out_v, out_g, out_b, cb);
    prep2_kernel<<<81, 72>>>(out_b);
    kA_kernel<<<128, 256, 147456>>>(z, in_b);
    kB_kernel<<<512, 256>>>(r_w1, r_b1, r_w2, r_b2, out);
    kC_kernel<<<128, 256, 149504>>>(out);
    kF_kernel<<<1, 128>>>(out);
}

// round 11
// speedup vs baseline: 1.3113x; 1.2417x over previous
#include <cuda_runtime.h>
#include <math.h>

#define NTOK 65536
#define CODES_OFF 33554432
#define LAT_OFF   34144256
#define COMMIT_OFF 38862848

// ---------------- device scratch (no allocation) ----------------
__device__ float g_P[72 * NTOK];      // [q][tok], q = i*8+d
__device__ float g_Q[72 * NTOK];      // selected raw code vecs, [q][tok]
__device__ float g_pr[9 * NTOK * 8];  // normalized probs per (stage, tok)
__device__ float g_WinT[512 * 72];    // [c][q]
__device__ float g_WoT[512 * 72];     // [c][q]
__device__ float g_M[81 * 64];        // M[i][j][d][e]
__device__ float g_cvec[81 * 8];      // W_in_i @ out_b_j
__device__ float g_Cbias[512];        // sum_j out_b_j
__device__ float g_cbn[9 * 8 * 128 * 8];  // normalized codebooks
__device__ float g_cn[9 * 8 * 128];       // raw norms
__device__ float g_cnt[72];
__device__ float g_ps[72];
__device__ float g_commit[1];

// ---------------- packed f32x2 helpers ----------------
__device__ __forceinline__ unsigned long long pack2(float lo, float hi) {
    unsigned long long r;
    asm("mov.b64 %0, {%1,%2};" : "=l"(r) : "f"(lo), "f"(hi));
    return r;
}
__device__ __forceinline__ void unpack2(unsigned long long v, float& lo, float& hi) {
    asm("mov.b64 {%0,%1}, %2;" : "=f"(lo), "=f"(hi) : "l"(v));
}
__device__ __forceinline__ unsigned long long fma2(unsigned long long a,
                                                   unsigned long long b,
                                                   unsigned long long c) {
    unsigned long long r;
    asm("fma.rn.f32x2 %0, %1, %2, %3;" : "=l"(r) : "l"(a), "l"(b), "l"(c));
    return r;
}
__device__ __forceinline__ unsigned long long add2(unsigned long long a,
                                                   unsigned long long b) {
    unsigned long long r;
    asm("add.rn.f32x2 %0, %1, %2;" : "=l"(r) : "l"(a), "l"(b));
    return r;
}

// ================================================================
// prep1: weight-norm weights (transposed), codebook norms, Cbias, zeros
// ================================================================
__global__ void prep1_kernel(const float* __restrict__ in_v, const float* __restrict__ in_g,
                             const float* __restrict__ out_v, const float* __restrict__ out_g,
                             const float* __restrict__ out_b, const float* __restrict__ cb) {
    int tid = blockIdx.x * blockDim.x + threadIdx.x;
    if (tid < 72) {
        const float* v = in_v + (size_t)tid * 512;
        float s = 0.f;
        for (int c = 0; c < 512; c++) s = fmaf(v[c], v[c], s);
        float inv = in_g[tid] / sqrtf(s);
        for (int c = 0; c < 512; c++) g_WinT[c * 72 + tid] = v[c] * inv;
    } else if (tid < 72 + 4608) {
        int rid = tid - 72;                       // j*512 + c
        int j = rid >> 9, c = rid & 511;
        const float* v = out_v + (size_t)rid * 8;
        float s = 0.f;
#pragma unroll
        for (int d = 0; d < 8; d++) s = fmaf(v[d], v[d], s);
        float inv = out_g[rid] / sqrtf(s);
#pragma unroll
        for (int d = 0; d < 8; d++) g_WoT[c * 72 + j * 8 + d] = v[d] * inv;
    } else if (tid < 4680 + 512) {
        int c = tid - 4680;
        float s = 0.f;
        for (int j = 0; j < 9; j++) s += out_b[j * 512 + c];
        g_Cbias[c] = s;
    } else if (tid < 5192 + 9216) {
        int rid = tid - 5192;                     // i*1024 + e*128 + k
        const float* v = cb + (size_t)rid * 8;
        float s = 0.f;
#pragma unroll
        for (int d = 0; d < 8; d++) s = fmaf(v[d], v[d], s);
        float rawn = sqrtf(s);
        float m = fmaxf(rawn, 1e-12f);
#pragma unroll
        for (int d = 0; d < 8; d++) g_cbn[rid * 8 + d] = v[d] / m;
        g_cn[rid] = rawn;
    } else if (tid < 14408 + 145) {
        int r = tid - 14408;
        if (r < 72) g_cnt[r] = 0.f;
        else if (r < 144) g_ps[r - 72] = 0.f;
        else g_commit[0] = 0.f;
    }
}

// ================================================================
// prep2: M[i][j] = W_in_i @ W_out_j, cvec[i][j] = W_in_i @ out_b_j
// ================================================================
__global__ void prep2_kernel(const float* __restrict__ out_b) {
    int ij = blockIdx.x;              // i*9+j
    int i = ij / 9, j = ij % 9;
    int tid = threadIdx.x;            // 72 threads
    if (tid < 64) {
        int d = tid >> 3, e = tid & 7;
        float s = 0.f;
        for (int c = 0; c < 512; c++)
            s = fmaf(g_WinT[c * 72 + i * 8 + d], g_WoT[c * 72 + j * 8 + e], s);
        g_M[ij * 64 + d * 8 + e] = s;
    } else {
        int d = tid - 64;
        float s = 0.f;
        for (int c = 0; c < 512; c++)
            s = fmaf(g_WinT[c * 72 + i * 8 + d], out_b[j * 512 + c], s);
        g_cvec[ij * 8 + d] = s;
    }
}

// ================================================================
// kernel A: P = W_in_all @ z + in_b.
// grid 256: block = (token tile of 512) x (q-half of 36).
// Thread: 2 adjacent tokens x 18 q-pairs, 36 packed accumulators.
// smem: 512 x 36 half-weights (73728 B) -> 2-3 blocks/SM.
// ================================================================
__global__ __launch_bounds__(256) void kA_kernel(const float* __restrict__ z,
                                                 const float* __restrict__ in_b) {
    extern __shared__ float ws[];     // 512*36 floats
    int tid = threadIdx.x;
    int qh = blockIdx.x & 1;
    int tileBase = (blockIdx.x >> 1) * 512;

    // stage half-weights: ws[c*36 + j] = g_WinT[c*72 + qh*36 + j]
    for (int g = tid; g < 512 * 9; g += 256) {
        int c = g / 9, j4 = g % 9;
        ((float4*)ws)[c * 9 + j4] = *(const float4*)(g_WinT + c * 72 + qh * 36 + j4 * 4);
    }
    __syncthreads();

    int tok0 = tileBase + 2 * tid;
    int b = tok0 >> 12, t0 = tok0 & 4095;

    unsigned long long a0[18], a1[18];
#pragma unroll
    for (int m = 0; m < 18; m++) { a0[m] = 0ULL; a1[m] = 0ULL; }

    const float* zp = z + (size_t)b * 512 * 4096 + t0;
#pragma unroll 1
    for (int c0 = 0; c0 < 512; c0 += 8) {
        float2 zv[8];
#pragma unroll
        for (int cc = 0; cc < 8; cc++)
            zv[cc] = *(const float2*)(zp + (size_t)(c0 + cc) * 4096);
#pragma unroll
        for (int cc = 0; cc < 8; cc++) {
            unsigned long long za = pack2(zv[cc].x, zv[cc].x);
            unsigned long long zb = pack2(zv[cc].y, zv[cc].y);
            const ulonglong2* wrow = (const ulonglong2*)(ws + (c0 + cc) * 36);
#pragma unroll
            for (int m = 0; m < 9; m++) {
                ulonglong2 w = wrow[m];
                a0[2 * m]     = fma2(w.x, za, a0[2 * m]);
                a0[2 * m + 1] = fma2(w.y, za, a0[2 * m + 1]);
                a1[2 * m]     = fma2(w.x, zb, a1[2 * m]);
                a1[2 * m + 1] = fma2(w.y, zb, a1[2 * m + 1]);
            }
        }
    }
#pragma unroll
    for (int m = 0; m < 18; m++) {
        int q = qh * 36 + 2 * m;
        float l0, h0, l1, h1;
        unpack2(a0[m], l0, h0);      // token0: q, q+1
        unpack2(a1[m], l1, h1);      // token1
        float be = __ldg(&in_b[q]), bo = __ldg(&in_b[q + 1]);
        *(float2*)&g_P[(size_t)q * NTOK + tok0]       = make_float2(l0 + be, l1 + be);
        *(float2*)&g_P[(size_t)(q + 1) * NTOK + tok0] = make_float2(h0 + bo, h1 + bo);
    }
}

// ================================================================
// kernel B: per-token sequential RVQ, 1 thread/token, stages unrolled,
// q history in registers. grid 256 x 256.
// ================================================================
__global__ __launch_bounds__(256, 2) void kB_kernel(const float* __restrict__ r_w1,
                                                    const float* __restrict__ r_b1,
                                                    const float* __restrict__ r_w2,
                                                    const float* __restrict__ r_b2,
                                                    float* __restrict__ out) {
    extern __shared__ float4 sm4[];
    float4* s_cb = sm4;                       // 2056 float4 (expert stride 1028 floats)
    float* fb = (float*)(sm4 + 2056);
    float* s_M    = fb;                       // 5184
    float* s_cvec = s_M + 5184;               // 648
    float* s_w1   = s_cvec + 648;             // 576
    float* s_b1   = s_w1 + 576;               // 72
    float* s_w2   = s_b1 + 72;                // 576
    float* s_b2   = s_w2 + 576;               // 72
    float* s_red  = s_b2 + 72;                // 8

    int tid = threadIdx.x, lane = tid & 31, wid = tid >> 5;
    int tok = blockIdx.x * 256 + tid;
    int b = tok >> 12, t = tok & 4095;

    // one-time staging (ordered by the stage-0 barrier below)
    for (int j = tid; j < 5184; j += 256) s_M[j] = g_M[j];
    for (int j = tid; j < 648; j += 256) s_cvec[j] = g_cvec[j];
    for (int j = tid; j < 576; j += 256) { s_w1[j] = r_w1[j]; s_w2[j] = r_w2[j]; }
    if (tid < 72) { s_b1[tid] = r_b1[tid]; s_b2[tid] = r_b2[tid]; }

    float q_hist[72];
    float commit_loc = 0.f;
    float* out_codes = out + CODES_OFF;
    float* out_lat = out + LAT_OFF;

#pragma unroll
    for (int i = 0; i < 9; i++) {
        __syncthreads();
        {   // stage codebook into padded smem
            const float4* src = (const float4*)(g_cbn + (size_t)i * 8192);
#pragma unroll
            for (int j = 0; j < 8; j++) {
                int g = tid + j * 256;
                int e = g >> 8, r = g & 255;
                s_cb[e * 257 + r] = src[g];
            }
        }
        __syncthreads();

        // z_e = P_i - sum_{j<i} (M_ij q_j + c_ij), q from registers
        float ze[8];
#pragma unroll
        for (int d = 0; d < 8; d++) ze[d] = g_P[(size_t)(i * 8 + d) * NTOK + tok];
#pragma unroll
        for (int j = 0; j < i; j++) {
            const float* Mij = s_M + (i * 9 + j) * 64;
            const float* cij = s_cvec + (i * 9 + j) * 8;
#pragma unroll
            for (int d = 0; d < 8; d++) {
                float s = cij[d];
#pragma unroll
                for (int e = 0; e < 8; e++) s = fmaf(Mij[d * 8 + e], q_hist[j * 8 + e], s);
                ze[d] -= s;
            }
        }

        // latents output
        {
            float4* lp = (float4*)(out_lat + ((size_t)((b * 9 + i) * 4096 + t)) * 8);
            lp[0] = make_float4(ze[0], ze[1], ze[2], ze[3]);
            lp[1] = make_float4(ze[4], ze[5], ze[6], ze[7]);
        }

        // router (weights in smem, broadcast)
        float h[8];
#pragma unroll
        for (int hh = 0; hh < 8; hh++) {
            float s = s_b1[i * 8 + hh];
#pragma unroll
            for (int d = 0; d < 8; d++) s = fmaf(s_w1[(i * 8 + hh) * 8 + d], ze[d], s);
            h[hh] = fmaxf(s, 0.f);
        }
        float lg[8];
        float lmax = -3.4e38f;
        int estar = 0;
#pragma unroll
        for (int e = 0; e < 8; e++) {
            float s = s_b2[i * 8 + e];
#pragma unroll
            for (int hh = 0; hh < 8; hh++) s = fmaf(s_w2[(i * 8 + e) * 8 + hh], h[hh], s);
            lg[e] = s;
            if (s > lmax) { lmax = s; estar = e; }
        }

        // normalized probs -> global (aux loss computed by kR)
        float pr[8], psum = 0.f;
#pragma unroll
        for (int e = 0; e < 8; e++) { pr[e] = expf(lg[e] - lmax); psum += pr[e]; }
        float pinv = 1.f / psum;
        {
            float4* pp = (float4*)(g_pr + ((size_t)i * NTOK + tok) * 8);
            pp[0] = make_float4(pr[0] * pinv, pr[1] * pinv, pr[2] * pinv, pr[3] * pinv);
            pp[1] = make_float4(pr[4] * pinv, pr[5] * pinv, pr[6] * pinv, pr[7] * pinv);
        }

        // nearest neighbor: argmax_k ze . cbn_k  (|cbn|=1, scale-invariant)
        const float4* cpe = s_cb + estar * 257;
        float best = -3.4e38f;
        int bk = 0;
#pragma unroll 4
        for (int k = 0; k < 128; k++) {
            float4 a = cpe[2 * k], c = cpe[2 * k + 1];
            float dt = fmaf(ze[0], a.x, fmaf(ze[1], a.y, fmaf(ze[2], a.z, ze[3] * a.w)));
            dt = fmaf(ze[4], c.x, fmaf(ze[5], c.y, fmaf(ze[6], c.z, fmaf(ze[7], c.w, dt))));
            if (dt > best) { best = dt; bk = k; }
        }

        float cn = __ldg(&g_cn[i * 1024 + estar * 128 + bk]);
        float4 a = cpe[2 * bk], c = cpe[2 * bk + 1];
        float q[8] = { a.x * cn, a.y * cn, a.z * cn, a.w * cn,
                       c.x * cn, c.y * cn, c.z * cn, c.w * cn };
#pragma unroll
        for (int d = 0; d < 8; d++) {
            q_hist[i * 8 + d] = q[d];
            g_Q[(size_t)(i * 8 + d) * NTOK + tok] = q[d];
            float df = ze[d] - q[d];
            commit_loc = fmaf(df, df, commit_loc);
        }
        out_codes[(size_t)(b * 9 + i) * 4096 + t] = (float)(bk + 128 * estar);
    }

    // reduce commitment
    commit_loc += __shfl_xor_sync(0xffffffffu, commit_loc, 16);
    commit_loc += __shfl_xor_sync(0xffffffffu, commit_loc, 8);
    commit_loc += __shfl_xor_sync(0xffffffffu, commit_loc, 4);
    commit_loc += __shfl_xor_sync(0xffffffffu, commit_loc, 2);
    commit_loc += __shfl_xor_sync(0xffffffffu, commit_loc, 1);
    __syncthreads();
    if (lane == 0) s_red[wid] = commit_loc;
    __syncthreads();
    if (tid == 0) {
        float s = 0.f;
        for (int w = 0; w < 8; w++) s += s_red[w];
        atomicAdd(&g_commit[0], s);
    }
}

// ================================================================
// kernel R: reduce g_pr -> per-(stage,expert) prob sums + argmax counts
// ================================================================
__global__ void kR_kernel() {
    int i = blockIdx.x >> 5, chunk = blockIdx.x & 31;
    int tid = threadIdx.x, lane = tid & 31;
    float ps[8] = {0, 0, 0, 0, 0, 0, 0, 0};
    float cnt[8] = {0, 0, 0, 0, 0, 0, 0, 0};
    const float4* base = (const float4*)(g_pr + (size_t)i * NTOK * 8);
    int tok0 = chunk * 2048 + tid * 8;
#pragma unroll
    for (int u = 0; u < 8; u++) {
        int tok = tok0 + u;
        float4 v0 = base[tok * 2], v1 = base[tok * 2 + 1];
        float v[8] = {v0.x, v0.y, v0.z, v0.w, v1.x, v1.y, v1.z, v1.w};
        int am = 0;
        float m = v[0];
#pragma unroll
        for (int e = 1; e < 8; e++) if (v[e] > m) { m = v[e]; am = e; }
#pragma unroll
        for (int e = 0; e < 8; e++) {
            ps[e] += v[e];
            cnt[e] += (am == e) ? 1.f : 0.f;
        }
    }
#pragma unroll
    for (int e = 0; e < 8; e++) {
        for (int s = 16; s; s >>= 1) {
            ps[e] += __shfl_xor_sync(0xffffffffu, ps[e], s);
            cnt[e] += __shfl_xor_sync(0xffffffffu, cnt[e], s);
        }
    }
    if (lane == 0) {
#pragma unroll
        for (int e = 0; e < 8; e++) {
            atomicAdd(&g_ps[i * 8 + e], ps[e]);
            atomicAdd(&g_cnt[i * 8 + e], cnt[e]);
        }
    }
}

// ================================================================
// kernel C: z_q = W_out_cat @ Q + Cbias.
// grid 512: block = (token tile of 256) x (c-half of 256).
// Thread: 1 token, q2[36] packed regs. smem: 256x72 weights + 256 bias.
// ================================================================
__global__ __launch_bounds__(256) void kC_kernel(float* __restrict__ out) {
    extern __shared__ float sm[];          // 256*72 + 256 floats
    float* ws = sm;
    float* cbias = sm + 256 * 72;
    int tid = threadIdx.x;
    int ch = blockIdx.x & 1;
    int tok = (blockIdx.x >> 1) * 256 + tid;
    int cbase = ch * 256;
    int b = tok >> 12, t = tok & 4095;

    for (int g = tid; g < 256 * 18; g += 256) {
        int cr = g / 18, j4 = g % 18;
        ((float4*)ws)[cr * 18 + j4] = *(const float4*)(g_WoT + (size_t)(cbase + cr) * 72 + j4 * 4);
    }
    if (tid < 256) cbias[tid] = g_Cbias[cbase + tid];
    __syncthreads();

    unsigned long long q2[36];
#pragma unroll
    for (int m = 0; m < 36; m++)
        q2[m] = pack2(g_Q[(size_t)(2 * m) * NTOK + tok], g_Q[(size_t)(2 * m + 1) * NTOK + tok]);

    float* op = out + (size_t)b * 512 * 4096 + (size_t)cbase * 4096 + t;
#pragma unroll 2
    for (int cr = 0; cr < 256; cr++) {
        const ulonglong2* wr = (const ulonglong2*)(ws + cr * 72);
        unsigned long long ac0 = 0ULL, ac1 = 0ULL, ac2 = 0ULL, ac3 = 0ULL;
#pragma unroll
        for (int m = 0; m < 9; m++) {
            ulonglong2 w0 = wr[2 * m];
            ulonglong2 w1 = wr[2 * m + 1];
            ac0 = fma2(w0.x, q2[4 * m], ac0);
            ac1 = fma2(w0.y, q2[4 * m + 1], ac1);
            ac2 = fma2(w1.x, q2[4 * m + 2], ac2);
            ac3 = fma2(w1.y, q2[4 * m + 3], ac3);
        }
        unsigned long long s = add2(add2(ac0, ac1), add2(ac2, ac3));
        float lo, hi;
        unpack2(s, lo, hi);
        op[(size_t)cr * 4096] = lo + hi + cbias[cr];
    }
}

// ================================================================
// final: losses
// ================================================================
__global__ void kF_kernel(float* __restrict__ out) {
    __shared__ float sa[72];
    int tid = threadIdx.x;
    if (tid < 72) sa[tid] = g_cnt[tid] * g_ps[tid];
    __syncthreads();
    if (tid == 0) {
        float aux = 0.f;
        for (int q = 0; q < 72; q++) aux += sa[q];
        aux *= (1.f / 65536.f) * (1.f / 65536.f);
        float cm = g_commit[0] / 524288.f;    // /(16*4096*8)
        out[COMMIT_OFF] = cm;
        out[COMMIT_OFF + 1] = cm;             // codebook_loss == commitment_loss numerically
        out[COMMIT_OFF + 2] = aux;
    }
}

// ================================================================
extern "C" void kernel_launch(void* const* d_in, const int* in_sizes, int n_in,
                              void* d_out, int out_size) {
    const float* z     = (const float*)d_in[0];
    const float* in_v  = (const float*)d_in[1];
    const float* in_g  = (const float*)d_in[2];
    const float* in_b  = (const float*)d_in[3];
    const float* out_v = (const float*)d_in[4];
    const float* out_g = (const float*)d_in[5];
    const float* out_b = (const float*)d_in[6];
    const float* r_w1  = (const float*)d_in[7];
    const float* r_b1  = (const float*)d_in[8];
    const float* r_w2  = (const float*)d_in[9];
    const float* r_b2  = (const float*)d_in[10];
    const float* cb    = (const float*)d_in[11];
    float* out = (float*)d_out;

    cudaFuncSetAttribute(kA_kernel, cudaFuncAttributeMaxDynamicSharedMemorySize, 73728);
    cudaFuncSetAttribute(kB_kernel, cudaFuncAttributeMaxDynamicSharedMemorySize, 61440);
    cudaFuncSetAttribute(kC_kernel, cudaFuncAttributeMaxDynamicSharedMemorySize, 74752);

    prep1_kernel<<<57, 256>>>(in_v, in_g, out_v, out_g, out_b, cb);
    prep2_kernel<<<81, 72>>>(out_b);
    kA_kernel<<<256, 256, 73728>>>(z, in_b);
    kB_kernel<<<256, 256, 61440>>>(r_w1, r_b1, r_w2, r_b2, out);
    kR_kernel<<<288, 256>>>();
    kC_kernel<<<512, 256, 74752>>>(out);
    kF_kernel<<<1, 128>>>(out);
}